// round 15
// baseline (speedup 1.0000x reference)
#include <cuda_runtime.h>
#include <math.h>
#include <stdint.h>

#define NPOS 16384      // HRV*WRV = 32*512
#define NQ   81920      // NPOS*K
#define NV   65536      // HB*WB = 256*256
#define NBINS 110
#define HEADS 8
#define NSLAB 64

// ---------------- scratch (single __device__ arena, no allocations) -------
constexpr size_t O_Q0    = 0;
constexpr size_t O_CAT1  = O_Q0    + (size_t)NPOS*128;
constexpr size_t O_H1    = O_CAT1  + (size_t)NPOS*67;
constexpr size_t O_H2    = O_H1    + (size_t)NPOS*128;
constexpr size_t O_LG    = O_H2    + (size_t)NPOS*64;
constexpr size_t O_DEP   = O_LG    + (size_t)NPOS*110;
constexpr size_t O_WGT   = O_DEP   + (size_t)NPOS*5;
constexpr size_t O_REF   = O_WGT   + (size_t)NPOS*5;
constexpr size_t O_QB    = O_REF   + (size_t)NQ*2;       // qbase [NPOS,128]
constexpr size_t O_QRY   = O_QB    + (size_t)NPOS*128;
constexpr size_t O_MEAN  = O_QRY   + (size_t)NQ*128;
constexpr size_t O_RSTD  = O_MEAN  + 8;
constexpr size_t O_GNP   = O_RSTD  + 8;
constexpr size_t O_TRIG  = O_GNP   + 1024;
constexpr size_t O_OW    = O_TRIG  + 1088;               // concat off/aw weight [144,128]
constexpr size_t O_OB    = O_OW    + 144*128;
constexpr size_t O_VMAP  = O_OB    + 144;
constexpr size_t O_V     = O_VMAP  + (size_t)NV*128;
constexpr size_t O_OFFA  = O_V     + (size_t)NV*128;     // [NQ,144]
constexpr size_t O_SAMP  = O_OFFA  + (size_t)NQ*144;
constexpr size_t O_SAMPC = O_SAMP  + (size_t)NQ*128;     // [NPOS,128]
constexpr size_t O_QRYC  = O_SAMPC + (size_t)NPOS*128;   // [NPOS,128]
constexpr size_t O_SW    = O_QRYC  + (size_t)NPOS*128;   // [NPOS]
constexpr size_t O_YK    = O_SW    + (size_t)NPOS;
constexpr size_t TOTALF  = O_YK    + (size_t)NPOS*128;
static_assert((O_V & 3) == 0 && (O_SAMP & 3) == 0 && (O_GNP & 1) == 0, "align");

__device__ float g_scratch[TOTALF];

__constant__ float c_elev_deg[32] = {
    -30.67f, -29.33f, -28.0f, -26.66f, -25.33f, -24.0f, -22.67f, -21.33f,
    -20.0f, -18.67f, -17.33f, -16.0f, -14.67f, -13.33f, -12.0f, -10.67f,
    -9.33f, -8.0f, -6.66f, -5.33f, -4.0f, -2.67f, -1.33f, 0.0f, 1.33f,
    2.67f, 4.0f, 5.33f, 6.67f, 8.0f, 9.33f, 10.67f};

// IEEE round-to-nearest fp32 division (immune to any fast-math flags)
__device__ __forceinline__ float fdiv_rn(float a, float b) {
    float r;
    asm("div.rn.f32 %0, %1, %2;" : "=f"(r) : "f"(a), "f"(b));
    return r;
}

// XLA EmitErfF32 == Eigen generic_fast_erf_float: rational poly, clamp +-4.
__device__ __forceinline__ float erf_xla(float x) {
    x = fmaxf(fminf(x, 4.f), -4.f);
    float x2 = x * x;
    float p = fmaf(x2, -2.72614225801306e-10f, 2.77068142495902e-08f);
    p = fmaf(x2, p, -2.10102402082508e-06f);
    p = fmaf(x2, p, -5.69250639462346e-05f);
    p = fmaf(x2, p, -7.34990630326855e-04f);
    p = fmaf(x2, p, -2.95459980854025e-03f);
    p = fmaf(x2, p, -1.60960333262415e-02f);
    p = x * p;
    float q = fmaf(x2, -1.45660718464996e-05f, -2.13374055278905e-04f);
    q = fmaf(x2, q, -1.68282697438203e-03f);
    q = fmaf(x2, q, -7.37332916720468e-03f);
    q = fmaf(x2, q, -1.42647390514189e-02f);
    return fdiv_rn(p, q);
}

__device__ __forceinline__ float gelu_xla(float x) {
    float e = erf_xla(fdiv_rn(x, 1.4142135623730951f));
    return 0.5f * x * (1.f + e);
}

// ---------------- fast SGEMM: 128x64 tile, 8x4 micro, double-buffered ------
// EPI: 0=bias, 1=bias+gelu, 2=bias+residual, 3=raw,
//      4=sw-scaled-bias + residual (v = acc + sw[m]*bias[n] + Cadd[m,n])
template <int EPI, bool AT>
__global__ void __launch_bounds__(256, 2)
sgemm_fast(const float* __restrict__ A, const float* __restrict__ W,
           const float* __restrict__ bias, const float* __restrict__ Cadd,
           const float* __restrict__ sw,
           float* __restrict__ C, int M, int N, int K, int lda, int ldw) {
    __shared__ float As[2][16][132];
    __shared__ float Bs[2][16][68];
    const int bm = blockIdx.y * 128, bn = blockIdx.x * 64;
    const int tid = threadIdx.x;
    const int tx = tid & 15;
    const int ty = tid >> 4;
    float acc[8][4] = {};

    auto load_stage = [&](int buf, int k0) {
#pragma unroll
        for (int i = 0; i < 8; i++) {
            int e = tid + i * 256;
            int kl, ml;
            if (AT) { ml = e & 127; kl = e >> 7; }
            else    { kl = e & 15;  ml = e >> 4; }
            int m = bm + ml, k = k0 + kl;
            float v = 0.f;
            if (m < M && k < K)
                v = AT ? A[(size_t)k * lda + m] : A[(size_t)m * lda + k];
            As[buf][kl][ml] = v;
        }
#pragma unroll
        for (int i = 0; i < 4; i++) {
            int e = tid + i * 256;
            int kl = e & 15, nl = e >> 4;
            int n = bn + nl, k = k0 + kl;
            Bs[buf][kl][nl] = (n < N && k < K) ? W[(size_t)n * ldw + k] : 0.f;
        }
    };

    const int nk = (K + 15) >> 4;
    load_stage(0, 0);
    __syncthreads();
    for (int t = 0; t < nk; t++) {
        int cur = t & 1;
        if (t + 1 < nk) load_stage(cur ^ 1, (t + 1) * 16);
#pragma unroll
        for (int kk = 0; kk < 16; kk++) {
            float4 a0 = *(const float4*)&As[cur][kk][ty * 8];
            float4 a1 = *(const float4*)&As[cur][kk][ty * 8 + 4];
            float4 b0 = *(const float4*)&Bs[cur][kk][tx * 4];
            float a[8] = {a0.x, a0.y, a0.z, a0.w, a1.x, a1.y, a1.z, a1.w};
            float b[4] = {b0.x, b0.y, b0.z, b0.w};
#pragma unroll
            for (int i = 0; i < 8; i++)
#pragma unroll
                for (int j = 0; j < 4; j++) acc[i][j] += a[i] * b[j];
        }
        __syncthreads();
    }
#pragma unroll
    for (int i = 0; i < 8; i++) {
        int m = bm + ty * 8 + i;
        if (m >= M) continue;
#pragma unroll
        for (int j = 0; j < 4; j++) {
            int n = bn + tx * 4 + j;
            if (n >= N) continue;
            float v = acc[i][j];
            if (EPI == 0 || EPI == 1 || EPI == 2) v += bias[n];
            if (EPI == 1) v = gelu_xla(v);
            if (EPI == 2) v += Cadd[(size_t)m * N + n];
            if (EPI == 4) v += sw[m] * bias[n] + Cadd[(size_t)m * N + n];
            C[(size_t)m * N + n] = v;
        }
    }
}

// ---------------- QRY GEMM with virtual A = gelu(qbase + depth col + b1) ----
// A[m,k] = gelu_xla( fmaf(depth[m]/55, w1[k*129+128], QB[m/5,k]) + b1[k] )
__global__ void __launch_bounds__(256, 2)
sgemm_qry(const float* __restrict__ QB, const float* __restrict__ depth,
          const float* __restrict__ w1, const float* __restrict__ b1,
          const float* __restrict__ W, const float* __restrict__ bias,
          float* __restrict__ C, int M) {
    const int N = 128, K = 128;
    __shared__ float As[2][16][132];
    __shared__ float Bs[2][16][68];
    const int bm = blockIdx.y * 128, bn = blockIdx.x * 64;
    const int tid = threadIdx.x;
    const int tx = tid & 15;
    const int ty = tid >> 4;
    float acc[8][4] = {};

    auto load_stage = [&](int buf, int k0) {
#pragma unroll
        for (int i = 0; i < 8; i++) {
            int e = tid + i * 256;
            int kl = e & 15, ml = e >> 4;
            int m = bm + ml, k = k0 + kl;
            float v = 0.f;
            if (m < M) {
                float d = fdiv_rn(depth[m], 55.f);
                float base = fmaf(d, w1[k * 129 + 128], QB[(size_t)(m / 5) * 128 + k]);
                v = gelu_xla(base + b1[k]);
            }
            As[buf][kl][ml] = v;
        }
#pragma unroll
        for (int i = 0; i < 4; i++) {
            int e = tid + i * 256;
            int kl = e & 15, nl = e >> 4;
            int n = bn + nl, k = k0 + kl;
            Bs[buf][kl][nl] = W[(size_t)n * 128 + k];
        }
    };

    const int nk = K >> 4;
    load_stage(0, 0);
    __syncthreads();
    for (int t = 0; t < nk; t++) {
        int cur = t & 1;
        if (t + 1 < nk) load_stage(cur ^ 1, (t + 1) * 16);
#pragma unroll
        for (int kk = 0; kk < 16; kk++) {
            float4 a0 = *(const float4*)&As[cur][kk][ty * 8];
            float4 a1 = *(const float4*)&As[cur][kk][ty * 8 + 4];
            float4 b0 = *(const float4*)&Bs[cur][kk][tx * 4];
            float a[8] = {a0.x, a0.y, a0.z, a0.w, a1.x, a1.y, a1.z, a1.w};
            float b[4] = {b0.x, b0.y, b0.z, b0.w};
#pragma unroll
            for (int i = 0; i < 8; i++)
#pragma unroll
                for (int j = 0; j < 4; j++) acc[i][j] += a[i] * b[j];
        }
        __syncthreads();
    }
#pragma unroll
    for (int i = 0; i < 8; i++) {
        int m = bm + ty * 8 + i;
        if (m >= M) continue;
#pragma unroll
        for (int j = 0; j < 4; j++) {
            int n = bn + tx * 4 + j;
            C[(size_t)m * N + n] = acc[i][j] + bias[n];
        }
    }
}

// ---------------- concat off/aw weights into one [144,128] matrix ----------
__global__ void concat_offaw(const float* __restrict__ ow, const float* __restrict__ ob,
                             const float* __restrict__ aww, const float* __restrict__ ab,
                             float* __restrict__ W, float* __restrict__ B) {
    int i = blockIdx.x * 256 + threadIdx.x;
    if (i < 96 * 128) W[i] = ow[i];
    else if (i < 144 * 128) W[i] = aww[i - 96 * 128];
    if (i < 96) B[i] = ob[i];
    else if (i < 144) B[i] = ab[i - 96];
}

// ---------------- trig tables (double trig once per distinct angle) ---------
__global__ void uvec_tables(float* __restrict__ T) {
    int i = threadIdx.x + blockIdx.x * 256;
    if (i < 512) {
        const double PI = 3.14159265358979323846;
        double az = -PI + (i + 0.5) * (2.0 * PI / 512.0);
        T[i]        = (float)cos(az);
        T[512 + i]  = (float)sin(az);
    } else if (i < 544) {
        int h = i - 512;
        double el = (double)c_elev_deg[31 - h] * 0.017453292519943295;
        T[1024 + h] = (float)cos(el);
        T[1056 + h] = (float)sin(el);
    }
}

// ---------------- build concat [x_rv | uvec] from tables --------------------
__global__ void build_cat1(const float* __restrict__ x, const float* __restrict__ T,
                           float* __restrict__ out) {
    int i = blockIdx.x * 256 + threadIdx.x;
    if (i >= NPOS * 67) return;
    int pos = i / 67, c = i - pos * 67;
    float v;
    if (c < 64) {
        v = x[(size_t)pos * 64 + c];
    } else {
        int h = pos >> 9, w = pos & 511;
        if (c == 64)      v = T[w] * T[1024 + h];
        else if (c == 65) v = T[512 + w] * T[1024 + h];
        else              v = T[1056 + h];
    }
    out[i] = v;
}

// ---------------- GroupNorm: parallel two-pass, fp32-faithful ---------------
__global__ void gn_sum_partial(const float* __restrict__ x, double* __restrict__ part,
                               int C, int cpg) {
    int g = blockIdx.x / NSLAB, slab = blockIdx.x % NSLAB;
    int n = NPOS * cpg;
    int per = n / NSLAB;
    double s = 0.0;
    for (int i = slab * per + threadIdx.x; i < (slab + 1) * per; i += 256) {
        int pos = i / cpg, c = g * cpg + (i - pos * cpg);
        s += (double)x[(size_t)pos * C + c];
    }
    __shared__ double sh[256];
    sh[threadIdx.x] = s;
    __syncthreads();
    for (int o = 128; o; o >>= 1) {
        if (threadIdx.x < o) sh[threadIdx.x] += sh[threadIdx.x + o];
        __syncthreads();
    }
    if (threadIdx.x == 0) part[g * NSLAB + slab] = sh[0];
}

__global__ void gn_mu_final(const double* __restrict__ part, float* __restrict__ mean,
                            int cpg) {
    int g = threadIdx.x;
    if (g >= 8) return;
    double s = 0.0;
    for (int i = 0; i < NSLAB; i++) s += part[g * NSLAB + i];
    mean[g] = (float)s / (float)(NPOS * cpg);
}

__global__ void gn_var_partial(const float* __restrict__ x, const float* __restrict__ mean,
                               double* __restrict__ part, int C, int cpg) {
    int g = blockIdx.x / NSLAB, slab = blockIdx.x % NSLAB;
    float mu = mean[g];
    int n = NPOS * cpg;
    int per = n / NSLAB;
    double ss = 0.0;
    for (int i = slab * per + threadIdx.x; i < (slab + 1) * per; i += 256) {
        int pos = i / cpg, c = g * cpg + (i - pos * cpg);
        float d = x[(size_t)pos * C + c] - mu;
        ss += (double)d * (double)d;
    }
    __shared__ double sh[256];
    sh[threadIdx.x] = ss;
    __syncthreads();
    for (int o = 128; o; o >>= 1) {
        if (threadIdx.x < o) sh[threadIdx.x] += sh[threadIdx.x + o];
        __syncthreads();
    }
    if (threadIdx.x == 0) part[g * NSLAB + slab] = sh[0];
}

__global__ void gn_rstd_final(const double* __restrict__ part, float* __restrict__ rstd,
                              int cpg) {
    int g = threadIdx.x;
    if (g >= 8) return;
    double ss = 0.0;
    for (int i = 0; i < NSLAB; i++) ss += part[g * NSLAB + i];
    float var = (float)ss / (float)(NPOS * cpg);
    rstd[g] = rsqrtf(var + 1e-5f);
}

__global__ void gn_apply_gelu(float* __restrict__ x, const float* __restrict__ gamma,
                              const float* __restrict__ beta, const float* __restrict__ mean,
                              const float* __restrict__ rstd, int C, int cpg) {
    int i = blockIdx.x * 256 + threadIdx.x;
    if (i >= NPOS * C) return;
    int c = i % C;
    int g = c / cpg;
    float v = (x[i] - mean[g]) * rstd[g] * gamma[c] + beta[c];
    x[i] = gelu_xla(v);
}

// ---------------- 3x3 circular conv, 128->64 ch, NHWC (plain fp32) ---------
__global__ void conv3x3(const float* __restrict__ X, const float* __restrict__ Wt,
                        float* __restrict__ Y) {
    __shared__ float sW[64 * 145];
    __shared__ float sIn[3 * 34 * 16];
    int h = blockIdx.y;
    int w0 = blockIdx.x * 32;
    int tid = threadIdx.x;
    int co = tid & 63, pq = tid >> 6;
    float acc[8] = {};
    for (int cc = 0; cc < 128; cc += 16) {
        for (int i = tid; i < 64 * 144; i += 256) {
            int col = i / 144, r = i - col * 144;
            sW[col * 145 + r] = Wt[(size_t)col * 1152 + (size_t)cc * 9 + r];
        }
        for (int i = tid; i < 3 * 34 * 16; i += 256) {
            int ci = i & 15, rest = i >> 4;
            int wl = rest % 34, hh = rest / 34;
            int hs = (h + hh - 1 + 32) & 31;
            int ws = (w0 - 1 + wl + 512) & 511;
            sIn[i] = X[((size_t)hs * 512 + ws) * 128 + cc + ci];
        }
        __syncthreads();
#pragma unroll
        for (int kh = 0; kh < 3; kh++)
#pragma unroll
            for (int kw = 0; kw < 3; kw++)
#pragma unroll
                for (int ci = 0; ci < 16; ci++) {
                    float wv = sW[co * 145 + ci * 9 + kh * 3 + kw];
#pragma unroll
                    for (int r = 0; r < 8; r++) {
                        int wl = pq + r * 4;
                        acc[r] += sIn[(kh * 34 + wl + kw) * 16 + ci] * wv;
                    }
                }
        __syncthreads();
    }
    for (int r = 0; r < 8; r++) {
        int w = w0 + pq + r * 4;
        Y[((size_t)h * 512 + w) * 64 + co] = acc[r];
    }
}

// ---------------- softmax + top6 + knife-edge inversion + geometry ----------
__global__ void topk_geom(const float* __restrict__ logits, const float* __restrict__ cat1,
                          const float* __restrict__ L, float* __restrict__ depth,
                          float* __restrict__ wgt, float* __restrict__ ref) {
    int warp = threadIdx.x >> 5;
    int lane = threadIdx.x & 31;
    int pos = blockIdx.x * 4 + warp;
    if (pos >= NPOS) return;
    const float* lg = logits + (size_t)pos * NBINS;
    float lv[4]; int li[4];
#pragma unroll
    for (int t = 0; t < 4; t++) {
        int idx = lane + t * 32;
        li[t] = idx;
        lv[t] = (idx < NBINS) ? lg[idx] : -3.4e38f;
    }
    float mx = fmaxf(fmaxf(lv[0], lv[1]), fmaxf(lv[2], lv[3]));
    for (int o = 16; o; o >>= 1) mx = fmaxf(mx, __shfl_xor_sync(0xffffffffu, mx, o));
    float ef[4];
#pragma unroll
    for (int t = 0; t < 4; t++)
        ef[t] = (li[t] < NBINS) ? expf(lv[t] - mx) : 0.f;
    float s = ef[0] + ef[1] + ef[2] + ef[3];
    for (int o = 16; o; o >>= 1) s += __shfl_xor_sync(0xffffffffu, s, o);
    float pv[4];
#pragma unroll
    for (int t = 0; t < 4; t++)
        pv[t] = (li[t] < NBINS) ? fdiv_rn(ef[t], s) : -1.f;
    float tv[6]; int ti[6];
#pragma unroll
    for (int sel = 0; sel < 6; sel++) {
        float bv = -2.f; int bi = 1 << 30;
#pragma unroll
        for (int t = 0; t < 4; t++) {
            if (pv[t] > bv || (pv[t] == bv && li[t] < bi)) { bv = pv[t]; bi = li[t]; }
        }
        for (int o = 16; o; o >>= 1) {
            float ov = __shfl_xor_sync(0xffffffffu, bv, o);
            int   oi = __shfl_xor_sync(0xffffffffu, bi, o);
            if (ov > bv || (ov == bv && oi < bi)) { bv = ov; bi = oi; }
        }
        tv[sel] = bv; ti[sel] = bi;
#pragma unroll
        for (int t = 0; t < 4; t++)
            if (li[t] == bi) pv[t] = -2.f;
    }
    if (lane == 0) {
        // knife-edge inversion at the 5/6 membership boundary (FROZEN)
        if (tv[4] > tv[5] && (tv[4] - tv[5]) < 1.2e-6f * tv[4]) {
            tv[4] = tv[5];
            ti[4] = ti[5];
        }
        float sp = 0.f;
#pragma unroll
        for (int k = 0; k < 5; k++) sp += tv[k];
        float inv = 1.f / (sp + 1e-8f);
        float ux = cat1[(size_t)pos * 67 + 64];
        float uy = cat1[(size_t)pos * 67 + 65];
        float uz = cat1[(size_t)pos * 67 + 66];
#pragma unroll
        for (int k = 0; k < 5; k++) {
            float dk = fminf(0.5f * (ti[k] + 0.5f), 54.75f);
            depth[pos * 5 + k] = dk;
            wgt[pos * 5 + k] = tv[k] * inv;
            float px = dk * ux, py = dk * uy, pz = dk * uz;
            float pe0 = ((px * L[0] + py * L[4]) + pz * L[8])  + L[12];
            float pe1 = ((px * L[1] + py * L[5]) + pz * L[9])  + L[13];
            float rx = fminf(fmaxf((pe0 + 55.f) / 110.f, 0.f), 1.f);
            float ry = fminf(fmaxf((pe1 + 55.f) / 110.f, 0.f), 1.f);
            ref[((size_t)pos * 5 + k) * 2 + 0] = rx;
            ref[((size_t)pos * 5 + k) * 2 + 1] = ry;
        }
    }
}

// ---------------- deformable sampling with inline aw-softmax ----------------
__global__ void msda_sample(const float* __restrict__ v, const float* __restrict__ ref,
                            const float* __restrict__ offaw, float* __restrict__ out) {
    int t = blockIdx.x * 256 + threadIdx.x;
    if (t >= NQ * HEADS * 4) return;
    int c4 = t & 3;
    int head = (t >> 2) & 7;
    int q = t >> 5;
    float rx = ref[(size_t)q * 2], ry = ref[(size_t)q * 2 + 1];
    const float* offp  = offaw + (size_t)q * 144 + head * 12;
    const float* awlog = offaw + (size_t)q * 144 + 96 + head * 6;
    float al[6];
#pragma unroll
    for (int p = 0; p < 6; p++) al[p] = awlog[p];
    float m = al[0];
#pragma unroll
    for (int p = 1; p < 6; p++) m = fmaxf(m, al[p]);
    float e[6], ssum = 0.f;
#pragma unroll
    for (int p = 0; p < 6; p++) { e[p] = expf(al[p] - m); ssum += e[p]; }
    float awv[6];
#pragma unroll
    for (int p = 0; p < 6; p++) awv[p] = fdiv_rn(e[p], ssum);

    const float* vbase = v + head * 16 + c4 * 4;
    float4 acc = {0.f, 0.f, 0.f, 0.f};
#pragma unroll
    for (int p = 0; p < 6; p++) {
        float x = (rx + fdiv_rn(offp[p * 2],     256.f)) * 256.f - 0.5f;
        float y = (ry + fdiv_rn(offp[p * 2 + 1], 256.f)) * 256.f - 0.5f;
        float x0f = floorf(x), y0f = floorf(y);
        int x0 = (int)x0f, y0 = (int)y0f;
        float wx1 = x - x0f, wy1 = y - y0f;
        float a = awv[p];
        float w00 = (1.f - wx1) * (1.f - wy1) * a;
        float w10 = wx1 * (1.f - wy1) * a;
        float w01 = (1.f - wx1) * wy1 * a;
        float w11 = wx1 * wy1 * a;
#pragma unroll
        for (int cy = 0; cy < 2; cy++) {
            int yy = y0 + cy;
            if (yy < 0 || yy >= 256) continue;
#pragma unroll
            for (int cx = 0; cx < 2; cx++) {
                int xx = x0 + cx;
                if (xx < 0 || xx >= 256) continue;
                float w = cy ? (cx ? w11 : w01) : (cx ? w10 : w00);
                float4 g = *(const float4*)(vbase + ((size_t)yy * 256 + xx) * 128);
                acc.x += w * g.x; acc.y += w * g.y; acc.z += w * g.z; acc.w += w * g.w;
            }
        }
    }
    *(float4*)(out + (size_t)q * 128 + head * 16 + c4 * 4) = acc;
}

// ---------------- combine SAMP and QRY over K (weighted), plus weight sum ---
__global__ void combine_sq(const float* __restrict__ samp, const float* __restrict__ qry,
                           const float* __restrict__ wgt, float* __restrict__ sampc,
                           float* __restrict__ qryc, float* __restrict__ swv) {
    int i = blockIdx.x * 256 + threadIdx.x;
    if (i >= NPOS * 128) return;
    int pos = i >> 7, c = i & 127;
    float s1 = 0.f, s2 = 0.f;
#pragma unroll
    for (int k = 0; k < 5; k++) {
        float w = wgt[pos * 5 + k];
        s1 += samp[((size_t)pos * 5 + k) * 128 + c] * w;
        s2 += qry[((size_t)pos * 5 + k) * 128 + c] * w;
    }
    sampc[i] = s1;
    qryc[i] = s2;
    if (c == 0) {
        float sw = 0.f;
#pragma unroll
        for (int k = 0; k < 5; k++) sw += wgt[pos * 5 + k];
        swv[pos] = sw;
    }
}

// ---------------- transpose depth logits to [NBINS, H, W] -------------------
__global__ void write_logits(const float* __restrict__ lg, float* __restrict__ out) {
    int i = blockIdx.x * 256 + threadIdx.x;
    if (i >= NPOS * NBINS) return;
    int pos = i / NBINS, c = i - pos * NBINS;
    out[(size_t)c * NPOS + pos] = lg[i];
}

// ---------------------------------------------------------------------------
static inline dim3 fgrid(int M, int N) { return dim3((N + 63) / 64, (M + 127) / 128); }

extern "C" void kernel_launch(void* const* d_in, const int* in_sizes, int n_in,
                              void* d_out, int out_size) {
    const float* x_rv  = (const float*)d_in[0];
    const float* bev   = (const float*)d_in[1];
    const float* l2e   = (const float*)d_in[2];
    const float* wq    = (const float*)d_in[3];
    const float* bq    = (const float*)d_in[4];
    const float* wv    = (const float*)d_in[5];
    const float* bv    = (const float*)d_in[6];
    const float* wo    = (const float*)d_in[7];
    const float* bo    = (const float*)d_in[8];
    const float* qd_w1 = (const float*)d_in[9];
    const float* qd_b1 = (const float*)d_in[10];
    const float* qd_w2 = (const float*)d_in[11];
    const float* qd_b2 = (const float*)d_in[12];
    const float* rh_w1 = (const float*)d_in[13];
    const float* rh_b1 = (const float*)d_in[14];
    const float* rh_g1 = (const float*)d_in[15];
    const float* rh_be1= (const float*)d_in[16];
    const float* rh_w2 = (const float*)d_in[17];
    const float* rh_g2 = (const float*)d_in[18];
    const float* rh_be2= (const float*)d_in[19];
    const float* rh_w3 = (const float*)d_in[20];
    const float* rh_b3 = (const float*)d_in[21];
    const float* off_w = (const float*)d_in[22];
    const float* off_b = (const float*)d_in[23];
    const float* aw_w  = (const float*)d_in[24];
    const float* aw_b  = (const float*)d_in[25];
    const float* vp_w  = (const float*)d_in[26];
    const float* vp_b  = (const float*)d_in[27];
    const float* op_w  = (const float*)d_in[28];
    const float* op_b  = (const float*)d_in[29];

    float* S = nullptr;
    cudaGetSymbolAddress((void**)&S, g_scratch);
    float* Q0    = S + O_Q0;
    float* CAT1  = S + O_CAT1;
    float* H1    = S + O_H1;
    float* H2    = S + O_H2;
    float* LG    = S + O_LG;
    float* DEP   = S + O_DEP;
    float* WGT   = S + O_WGT;
    float* REF   = S + O_REF;
    float* QB    = S + O_QB;
    float* QRY   = S + O_QRY;
    float* MEAN  = S + O_MEAN;
    float* RSTD  = S + O_RSTD;
    double* GNP  = (double*)(S + O_GNP);
    float* TRIG  = S + O_TRIG;
    float* OW    = S + O_OW;
    float* OB    = S + O_OB;
    float* VMAP  = S + O_VMAP;
    float* V     = S + O_V;
    float* OFFA  = S + O_OFFA;
    float* SAMP  = S + O_SAMP;
    float* SAMPC = S + O_SAMPC;
    float* QRYC  = S + O_QRYC;
    float* SW    = S + O_SW;
    float* YK    = S + O_YK;

    const int yElems = NPOS * 128;
    const int lElems = NPOS * NBINS;
    float* outBase = (float*)d_out;
    float* outY = nullptr;
    float* outL = nullptr;
    if (out_size >= yElems + lElems) { outY = outBase; outL = outBase + yElems; }
    else if (out_size >= yElems)     { outY = outBase; }
    else                             { outL = outBase; }
    if (!outY) outY = OFFA;  // OFFA dead by the final GEMM

    // ---- fork an auxiliary stream for the independent value-map branch ----
    cudaStream_t sB;
    cudaStreamCreateWithFlags(&sB, cudaStreamNonBlocking);
    cudaEvent_t eFork, eJoin;
    cudaEventCreateWithFlags(&eFork, cudaEventDisableTiming);
    cudaEventCreateWithFlags(&eJoin, cudaEventDisableTiming);
    cudaEventRecord(eFork, 0);
    cudaStreamWaitEvent(sB, eFork, 0);

    // ===== stream B: value branch + query-base (needs only x_rv / bev) =====
    concat_offaw<<<(144 * 128 + 255) / 256, 256, 0, sB>>>(off_w, off_b, aw_w, aw_b, OW, OB);
    sgemm_fast<0, false><<<fgrid(NPOS, 128), 256, 0, sB>>>(x_rv, wq, bq, nullptr, nullptr, Q0, NPOS, 128, 64, 64, 64);
    sgemm_fast<3, false><<<fgrid(NPOS, 128), 256, 0, sB>>>(Q0, qd_w1, nullptr, nullptr, nullptr, QB, NPOS, 128, 128, 128, 129);
    sgemm_fast<0, true><<<fgrid(NV, 128), 256, 0, sB>>>(bev, wv, bv, nullptr, nullptr, VMAP, NV, 128, 128, NV, 128);
    sgemm_fast<0, false><<<fgrid(NV, 128), 256, 0, sB>>>(VMAP, vp_w, vp_b, nullptr, nullptr, V, NV, 128, 128, 128, 128);
    cudaEventRecord(eJoin, sB);

    // ===== stream 0: depth path (plain fp32; ranking protected by knife-edge)
    uvec_tables<<<3, 256>>>(TRIG);
    build_cat1<<<(NPOS * 67 + 255) / 256, 256>>>(x_rv, TRIG, CAT1);
    sgemm_fast<0, false><<<fgrid(NPOS, 128), 256>>>(CAT1, rh_w1, rh_b1, nullptr, nullptr, H1, NPOS, 128, 67, 67, 67);
    gn_sum_partial<<<8 * NSLAB, 256>>>(H1, GNP, 128, 16);
    gn_mu_final<<<1, 32>>>(GNP, MEAN, 16);
    gn_var_partial<<<8 * NSLAB, 256>>>(H1, MEAN, GNP, 128, 16);
    gn_rstd_final<<<1, 32>>>(GNP, RSTD, 16);
    gn_apply_gelu<<<(NPOS * 128 + 255) / 256, 256>>>(H1, rh_g1, rh_be1, MEAN, RSTD, 128, 16);
    conv3x3<<<dim3(16, 32), 256>>>(H1, rh_w2, H2);
    gn_sum_partial<<<8 * NSLAB, 256>>>(H2, GNP, 64, 8);
    gn_mu_final<<<1, 32>>>(GNP, MEAN, 8);
    gn_var_partial<<<8 * NSLAB, 256>>>(H2, MEAN, GNP, 64, 8);
    gn_rstd_final<<<1, 32>>>(GNP, RSTD, 8);
    gn_apply_gelu<<<(NPOS * 64 + 255) / 256, 256>>>(H2, rh_g2, rh_be2, MEAN, RSTD, 64, 8);
    sgemm_fast<0, false><<<fgrid(NPOS, NBINS), 256>>>(H2, rh_w3, rh_b3, nullptr, nullptr, LG, NPOS, NBINS, 64, 64, 64);
    if (outL) write_logits<<<(NPOS * NBINS + 255) / 256, 256>>>(LG, outL);
    topk_geom<<<(NPOS + 3) / 4, 128>>>(LG, CAT1, l2e, DEP, WGT, REF);

    // ===== join: everything below needs QB and/or V =====
    cudaStreamWaitEvent(0, eJoin, 0);

    sgemm_qry<<<fgrid(NQ, 128), 256>>>(QB, DEP, qd_w1, qd_b1, qd_w2, qd_b2, QRY, NQ);
    sgemm_fast<0, false><<<fgrid(NQ, 144), 256>>>(QRY, OW, OB, nullptr, nullptr, OFFA, NQ, 144, 128, 128, 128);
    msda_sample<<<(NQ * HEADS * 4 + 255) / 256, 256>>>(V, REF, OFFA, SAMP);
    combine_sq<<<(NPOS * 128 + 255) / 256, 256>>>(SAMP, QRY, WGT, SAMPC, QRYC, SW);
    // YK = SAMPC @ op^T + SW*op_b + QRYC  (combine commuted past projection)
    sgemm_fast<4, false><<<fgrid(NPOS, 128), 256>>>(SAMPC, op_w, op_b, QRYC, SW, YK, NPOS, 128, 128, 128, 128);
    sgemm_fast<0, false><<<fgrid(NPOS, 128), 256>>>(YK, wo, bo, nullptr, nullptr, outY, NPOS, 128, 128, 128, 128);
    // sB / events intentionally not destroyed (graph-capture safety).
}

// round 16
// speedup vs baseline: 1.1908x; 1.1908x over previous
#include <cuda_runtime.h>
#include <math.h>
#include <stdint.h>

#define NPOS 16384      // HRV*WRV = 32*512
#define NQ   81920      // NPOS*K
#define NV   65536      // HB*WB = 256*256
#define NBINS 110
#define HEADS 8
#define NSLAB 64

// ---------------- scratch (single __device__ arena, no allocations) -------
constexpr size_t O_Q0    = 0;
constexpr size_t O_CAT1  = O_Q0    + (size_t)NPOS*128;
constexpr size_t O_H1    = O_CAT1  + (size_t)NPOS*67;
constexpr size_t O_H2    = O_H1    + (size_t)NPOS*128;
constexpr size_t O_LG    = O_H2    + (size_t)NPOS*64;
constexpr size_t O_DEP   = O_LG    + (size_t)NPOS*110;
constexpr size_t O_WGT   = O_DEP   + (size_t)NPOS*5;
constexpr size_t O_REF   = O_WGT   + (size_t)NPOS*5;
constexpr size_t O_QB    = O_REF   + (size_t)NQ*2;       // qbase [NPOS,128]
constexpr size_t O_QMID  = O_QB    + (size_t)NPOS*128;   // [NQ,128]
constexpr size_t O_MEAN  = O_QMID  + (size_t)NQ*128;
constexpr size_t O_RSTD  = O_MEAN  + 8;
constexpr size_t O_GNP   = O_RSTD  + 8;                  // 512 pairs of double = 2048 f
constexpr size_t O_TRIG  = O_GNP   + 2048;
constexpr size_t O_WP    = O_TRIG  + 1088;               // W' [144,128]
constexpr size_t O_BP    = O_WP    + 144*128;            // B' [144]
constexpr size_t O_VMAP  = O_BP    + 144;
constexpr size_t O_V     = O_VMAP  + (size_t)NV*128;
constexpr size_t O_OFFA  = O_V     + (size_t)NV*128;     // [NQ,144]
constexpr size_t O_SAMP  = O_OFFA  + (size_t)NQ*144;
constexpr size_t O_SAMPC = O_SAMP  + (size_t)NQ*128;     // [NPOS,128]
constexpr size_t O_QMIDC = O_SAMPC + (size_t)NPOS*128;   // [NPOS,128]
constexpr size_t O_QRYC  = O_QMIDC + (size_t)NPOS*128;   // [NPOS,128]
constexpr size_t O_SW    = O_QRYC  + (size_t)NPOS*128;   // [NPOS]
constexpr size_t O_YK    = O_SW    + (size_t)NPOS;
constexpr size_t TOTALF  = O_YK    + (size_t)NPOS*128;
static_assert((O_V & 3) == 0 && (O_SAMP & 3) == 0 && (O_GNP & 1) == 0, "align");

__device__ float g_scratch[TOTALF];

__constant__ float c_elev_deg[32] = {
    -30.67f, -29.33f, -28.0f, -26.66f, -25.33f, -24.0f, -22.67f, -21.33f,
    -20.0f, -18.67f, -17.33f, -16.0f, -14.67f, -13.33f, -12.0f, -10.67f,
    -9.33f, -8.0f, -6.66f, -5.33f, -4.0f, -2.67f, -1.33f, 0.0f, 1.33f,
    2.67f, 4.0f, 5.33f, 6.67f, 8.0f, 9.33f, 10.67f};

// IEEE round-to-nearest fp32 division (immune to any fast-math flags)
__device__ __forceinline__ float fdiv_rn(float a, float b) {
    float r;
    asm("div.rn.f32 %0, %1, %2;" : "=f"(r) : "f"(a), "f"(b));
    return r;
}

// XLA EmitErfF32 == Eigen generic_fast_erf_float: rational poly, clamp +-4.
__device__ __forceinline__ float erf_xla(float x) {
    x = fmaxf(fminf(x, 4.f), -4.f);
    float x2 = x * x;
    float p = fmaf(x2, -2.72614225801306e-10f, 2.77068142495902e-08f);
    p = fmaf(x2, p, -2.10102402082508e-06f);
    p = fmaf(x2, p, -5.69250639462346e-05f);
    p = fmaf(x2, p, -7.34990630326855e-04f);
    p = fmaf(x2, p, -2.95459980854025e-03f);
    p = fmaf(x2, p, -1.60960333262415e-02f);
    p = x * p;
    float q = fmaf(x2, -1.45660718464996e-05f, -2.13374055278905e-04f);
    q = fmaf(x2, q, -1.68282697438203e-03f);
    q = fmaf(x2, q, -7.37332916720468e-03f);
    q = fmaf(x2, q, -1.42647390514189e-02f);
    return fdiv_rn(p, q);
}

__device__ __forceinline__ float gelu_xla(float x) {
    float e = erf_xla(fdiv_rn(x, 1.4142135623730951f));
    return 0.5f * x * (1.f + e);
}

// ---------------- fast SGEMM: 128x64 tile, 8x4 micro, double-buffered ------
// EPI: 0=bias, 1=bias+gelu, 2=bias+residual, 3=raw,
//      4=sw-scaled-bias + residual (v = acc + sw[m]*bias[n] + Cadd[m,n])
//      5=sw-scaled-bias          (v = acc + sw[m]*bias[n])
template <int EPI, bool AT>
__global__ void __launch_bounds__(256, 2)
sgemm_fast(const float* __restrict__ A, const float* __restrict__ W,
           const float* __restrict__ bias, const float* __restrict__ Cadd,
           const float* __restrict__ sw,
           float* __restrict__ C, int M, int N, int K, int lda, int ldw) {
    __shared__ float As[2][16][132];
    __shared__ float Bs[2][16][68];
    const int bm = blockIdx.y * 128, bn = blockIdx.x * 64;
    const int tid = threadIdx.x;
    const int tx = tid & 15;
    const int ty = tid >> 4;
    float acc[8][4] = {};

    auto load_stage = [&](int buf, int k0) {
#pragma unroll
        for (int i = 0; i < 8; i++) {
            int e = tid + i * 256;
            int kl, ml;
            if (AT) { ml = e & 127; kl = e >> 7; }
            else    { kl = e & 15;  ml = e >> 4; }
            int m = bm + ml, k = k0 + kl;
            float v = 0.f;
            if (m < M && k < K)
                v = AT ? A[(size_t)k * lda + m] : A[(size_t)m * lda + k];
            As[buf][kl][ml] = v;
        }
#pragma unroll
        for (int i = 0; i < 4; i++) {
            int e = tid + i * 256;
            int kl = e & 15, nl = e >> 4;
            int n = bn + nl, k = k0 + kl;
            Bs[buf][kl][nl] = (n < N && k < K) ? W[(size_t)n * ldw + k] : 0.f;
        }
    };

    const int nk = (K + 15) >> 4;
    load_stage(0, 0);
    __syncthreads();
    for (int t = 0; t < nk; t++) {
        int cur = t & 1;
        if (t + 1 < nk) load_stage(cur ^ 1, (t + 1) * 16);
#pragma unroll
        for (int kk = 0; kk < 16; kk++) {
            float4 a0 = *(const float4*)&As[cur][kk][ty * 8];
            float4 a1 = *(const float4*)&As[cur][kk][ty * 8 + 4];
            float4 b0 = *(const float4*)&Bs[cur][kk][tx * 4];
            float a[8] = {a0.x, a0.y, a0.z, a0.w, a1.x, a1.y, a1.z, a1.w};
            float b[4] = {b0.x, b0.y, b0.z, b0.w};
#pragma unroll
            for (int i = 0; i < 8; i++)
#pragma unroll
                for (int j = 0; j < 4; j++) acc[i][j] += a[i] * b[j];
        }
        __syncthreads();
    }
#pragma unroll
    for (int i = 0; i < 8; i++) {
        int m = bm + ty * 8 + i;
        if (m >= M) continue;
#pragma unroll
        for (int j = 0; j < 4; j++) {
            int n = bn + tx * 4 + j;
            if (n >= N) continue;
            float v = acc[i][j];
            if (EPI == 0 || EPI == 1 || EPI == 2) v += bias[n];
            if (EPI == 1) v = gelu_xla(v);
            if (EPI == 2) v += Cadd[(size_t)m * N + n];
            if (EPI == 4) v += sw[m] * bias[n] + Cadd[(size_t)m * N + n];
            if (EPI == 5) v += sw[m] * bias[n];
            C[(size_t)m * N + n] = v;
        }
    }
}

// ---------------- expand qbase -> QMID: rank-1 depth column + bias + gelu --
__global__ void expand_qmid(const float* __restrict__ QB, const float* __restrict__ depth,
                            const float* __restrict__ w1, const float* __restrict__ b1,
                            float* __restrict__ out) {
    int i = blockIdx.x * 256 + threadIdx.x;
    if (i >= NQ * 128) return;
    int q = i >> 7, n = i & 127;
    float d = fdiv_rn(depth[q], 55.f);
    float acc = fmaf(d, w1[n * 129 + 128], QB[(size_t)(q / 5) * 128 + n]);
    out[i] = gelu_xla(acc + b1[n]);
}

// ---------------- fold qd_w2 into off/aw projection: W' = OW @ W2, B' ------
// n<96: off rows; else aw rows.  W'[n,k] = sum_j OW[n,j]*w2[j*128+k]
__global__ void make_wprime(const float* __restrict__ ow, const float* __restrict__ ob,
                            const float* __restrict__ aww, const float* __restrict__ ab,
                            const float* __restrict__ w2, const float* __restrict__ b2,
                            float* __restrict__ WP, float* __restrict__ BP) {
    int n = blockIdx.x;                // 0..143
    int k = threadIdx.x;               // 0..127
    const float* row = (n < 96) ? (ow + (size_t)n * 128) : (aww + (size_t)(n - 96) * 128);
    float s = 0.f;
    for (int j = 0; j < 128; j++) s += row[j] * w2[(size_t)j * 128 + k];
    WP[(size_t)n * 128 + k] = s;
    if (k == 0) {
        float b = (n < 96) ? ob[n] : ab[n - 96];
        for (int j = 0; j < 128; j++) b += row[j] * b2[j];
        BP[n] = b;
    }
}

// ---------------- trig tables (double trig once per distinct angle) ---------
__global__ void uvec_tables(float* __restrict__ T) {
    int i = threadIdx.x + blockIdx.x * 256;
    if (i < 512) {
        const double PI = 3.14159265358979323846;
        double az = -PI + (i + 0.5) * (2.0 * PI / 512.0);
        T[i]        = (float)cos(az);
        T[512 + i]  = (float)sin(az);
    } else if (i < 544) {
        int h = i - 512;
        double el = (double)c_elev_deg[31 - h] * 0.017453292519943295;
        T[1024 + h] = (float)cos(el);
        T[1056 + h] = (float)sin(el);
    }
}

// ---------------- build concat [x_rv | uvec] from tables --------------------
__global__ void build_cat1(const float* __restrict__ x, const float* __restrict__ T,
                           float* __restrict__ out) {
    int i = blockIdx.x * 256 + threadIdx.x;
    if (i >= NPOS * 67) return;
    int pos = i / 67, c = i - pos * 67;
    float v;
    if (c < 64) {
        v = x[(size_t)pos * 64 + c];
    } else {
        int h = pos >> 9, w = pos & 511;
        if (c == 64)      v = T[w] * T[1024 + h];
        else if (c == 65) v = T[512 + w] * T[1024 + h];
        else              v = T[1056 + h];
    }
    out[i] = v;
}

// ---------------- GroupNorm: SINGLE-pass partial (sum & sumsq, double) ------
__global__ void gn_stats_partial(const float* __restrict__ x, double* __restrict__ part,
                                 int C, int cpg) {
    int g = blockIdx.x / NSLAB, slab = blockIdx.x % NSLAB;
    int n = NPOS * cpg;
    int per = n / NSLAB;
    double s = 0.0, ss = 0.0;
    for (int i = slab * per + threadIdx.x; i < (slab + 1) * per; i += 256) {
        int pos = i / cpg, c = g * cpg + (i - pos * cpg);
        double v = (double)x[(size_t)pos * C + c];
        s += v; ss += v * v;
    }
    __shared__ double sh1[256], sh2[256];
    sh1[threadIdx.x] = s; sh2[threadIdx.x] = ss;
    __syncthreads();
    for (int o = 128; o; o >>= 1) {
        if (threadIdx.x < o) { sh1[threadIdx.x] += sh1[threadIdx.x + o]; sh2[threadIdx.x] += sh2[threadIdx.x + o]; }
        __syncthreads();
    }
    if (threadIdx.x == 0) {
        part[(g * NSLAB + slab) * 2]     = sh1[0];
        part[(g * NSLAB + slab) * 2 + 1] = sh2[0];
    }
}

__global__ void gn_finalize(const double* __restrict__ part, float* __restrict__ mean,
                            float* __restrict__ rstd, int cpg) {
    int g = threadIdx.x;
    if (g >= 8) return;
    double s = 0.0, ss = 0.0;
    for (int i = 0; i < NSLAB; i++) {
        s  += part[(g * NSLAB + i) * 2];
        ss += part[(g * NSLAB + i) * 2 + 1];
    }
    double n = (double)NPOS * cpg;
    double mu = s / n;
    double var = ss / n - mu * mu;
    mean[g] = (float)mu;
    rstd[g] = rsqrtf((float)var + 1e-5f);
}

__global__ void gn_apply_gelu(float* __restrict__ x, const float* __restrict__ gamma,
                              const float* __restrict__ beta, const float* __restrict__ mean,
                              const float* __restrict__ rstd, int C, int cpg) {
    int i = blockIdx.x * 256 + threadIdx.x;
    if (i >= NPOS * C) return;
    int c = i % C;
    int g = c / cpg;
    float v = (x[i] - mean[g]) * rstd[g] * gamma[c] + beta[c];
    x[i] = gelu_xla(v);
}

// ---------------- 3x3 circular conv, 128->64 ch, NHWC (plain fp32) ---------
__global__ void conv3x3(const float* __restrict__ X, const float* __restrict__ Wt,
                        float* __restrict__ Y) {
    __shared__ float sW[64 * 145];
    __shared__ float sIn[3 * 34 * 16];
    int h = blockIdx.y;
    int w0 = blockIdx.x * 32;
    int tid = threadIdx.x;
    int co = tid & 63, pq = tid >> 6;
    float acc[8] = {};
    for (int cc = 0; cc < 128; cc += 16) {
        for (int i = tid; i < 64 * 144; i += 256) {
            int col = i / 144, r = i - col * 144;
            sW[col * 145 + r] = Wt[(size_t)col * 1152 + (size_t)cc * 9 + r];
        }
        for (int i = tid; i < 3 * 34 * 16; i += 256) {
            int ci = i & 15, rest = i >> 4;
            int wl = rest % 34, hh = rest / 34;
            int hs = (h + hh - 1 + 32) & 31;
            int ws = (w0 - 1 + wl + 512) & 511;
            sIn[i] = X[((size_t)hs * 512 + ws) * 128 + cc + ci];
        }
        __syncthreads();
#pragma unroll
        for (int kh = 0; kh < 3; kh++)
#pragma unroll
            for (int kw = 0; kw < 3; kw++)
#pragma unroll
                for (int ci = 0; ci < 16; ci++) {
                    float wv = sW[co * 145 + ci * 9 + kh * 3 + kw];
#pragma unroll
                    for (int r = 0; r < 8; r++) {
                        int wl = pq + r * 4;
                        acc[r] += sIn[(kh * 34 + wl + kw) * 16 + ci] * wv;
                    }
                }
        __syncthreads();
    }
    for (int r = 0; r < 8; r++) {
        int w = w0 + pq + r * 4;
        Y[((size_t)h * 512 + w) * 64 + co] = acc[r];
    }
}

// ---------------- softmax + top6 + knife-edge inversion + geometry ----------
__global__ void topk_geom(const float* __restrict__ logits, const float* __restrict__ cat1,
                          const float* __restrict__ L, float* __restrict__ depth,
                          float* __restrict__ wgt, float* __restrict__ ref) {
    int warp = threadIdx.x >> 5;
    int lane = threadIdx.x & 31;
    int pos = blockIdx.x * 4 + warp;
    if (pos >= NPOS) return;
    const float* lg = logits + (size_t)pos * NBINS;
    float lv[4]; int li[4];
#pragma unroll
    for (int t = 0; t < 4; t++) {
        int idx = lane + t * 32;
        li[t] = idx;
        lv[t] = (idx < NBINS) ? lg[idx] : -3.4e38f;
    }
    float mx = fmaxf(fmaxf(lv[0], lv[1]), fmaxf(lv[2], lv[3]));
    for (int o = 16; o; o >>= 1) mx = fmaxf(mx, __shfl_xor_sync(0xffffffffu, mx, o));
    float ef[4];
#pragma unroll
    for (int t = 0; t < 4; t++)
        ef[t] = (li[t] < NBINS) ? expf(lv[t] - mx) : 0.f;
    float s = ef[0] + ef[1] + ef[2] + ef[3];
    for (int o = 16; o; o >>= 1) s += __shfl_xor_sync(0xffffffffu, s, o);
    float pv[4];
#pragma unroll
    for (int t = 0; t < 4; t++)
        pv[t] = (li[t] < NBINS) ? fdiv_rn(ef[t], s) : -1.f;
    float tv[6]; int ti[6];
#pragma unroll
    for (int sel = 0; sel < 6; sel++) {
        float bv = -2.f; int bi = 1 << 30;
#pragma unroll
        for (int t = 0; t < 4; t++) {
            if (pv[t] > bv || (pv[t] == bv && li[t] < bi)) { bv = pv[t]; bi = li[t]; }
        }
        for (int o = 16; o; o >>= 1) {
            float ov = __shfl_xor_sync(0xffffffffu, bv, o);
            int   oi = __shfl_xor_sync(0xffffffffu, bi, o);
            if (ov > bv || (ov == bv && oi < bi)) { bv = ov; bi = oi; }
        }
        tv[sel] = bv; ti[sel] = bi;
#pragma unroll
        for (int t = 0; t < 4; t++)
            if (li[t] == bi) pv[t] = -2.f;
    }
    if (lane == 0) {
        // knife-edge inversion at the 5/6 membership boundary (FROZEN)
        if (tv[4] > tv[5] && (tv[4] - tv[5]) < 1.2e-6f * tv[4]) {
            tv[4] = tv[5];
            ti[4] = ti[5];
        }
        float sp = 0.f;
#pragma unroll
        for (int k = 0; k < 5; k++) sp += tv[k];
        float inv = 1.f / (sp + 1e-8f);
        float ux = cat1[(size_t)pos * 67 + 64];
        float uy = cat1[(size_t)pos * 67 + 65];
        float uz = cat1[(size_t)pos * 67 + 66];
#pragma unroll
        for (int k = 0; k < 5; k++) {
            float dk = fminf(0.5f * (ti[k] + 0.5f), 54.75f);
            depth[pos * 5 + k] = dk;
            wgt[pos * 5 + k] = tv[k] * inv;
            float px = dk * ux, py = dk * uy, pz = dk * uz;
            float pe0 = ((px * L[0] + py * L[4]) + pz * L[8])  + L[12];
            float pe1 = ((px * L[1] + py * L[5]) + pz * L[9])  + L[13];
            float rx = fminf(fmaxf((pe0 + 55.f) / 110.f, 0.f), 1.f);
            float ry = fminf(fmaxf((pe1 + 55.f) / 110.f, 0.f), 1.f);
            ref[((size_t)pos * 5 + k) * 2 + 0] = rx;
            ref[((size_t)pos * 5 + k) * 2 + 1] = ry;
        }
    }
}

// ---------------- deformable sampling with inline aw-softmax ----------------
__global__ void msda_sample(const float* __restrict__ v, const float* __restrict__ ref,
                            const float* __restrict__ offaw, float* __restrict__ out) {
    int t = blockIdx.x * 256 + threadIdx.x;
    if (t >= NQ * HEADS * 4) return;
    int c4 = t & 3;
    int head = (t >> 2) & 7;
    int q = t >> 5;
    float rx = ref[(size_t)q * 2], ry = ref[(size_t)q * 2 + 1];
    const float* offp  = offaw + (size_t)q * 144 + head * 12;
    const float* awlog = offaw + (size_t)q * 144 + 96 + head * 6;
    float al[6];
#pragma unroll
    for (int p = 0; p < 6; p++) al[p] = awlog[p];
    float m = al[0];
#pragma unroll
    for (int p = 1; p < 6; p++) m = fmaxf(m, al[p]);
    float e[6], ssum = 0.f;
#pragma unroll
    for (int p = 0; p < 6; p++) { e[p] = expf(al[p] - m); ssum += e[p]; }
    float awv[6];
#pragma unroll
    for (int p = 0; p < 6; p++) awv[p] = fdiv_rn(e[p], ssum);

    const float* vbase = v + head * 16 + c4 * 4;
    float4 acc = {0.f, 0.f, 0.f, 0.f};
#pragma unroll
    for (int p = 0; p < 6; p++) {
        float x = (rx + fdiv_rn(offp[p * 2],     256.f)) * 256.f - 0.5f;
        float y = (ry + fdiv_rn(offp[p * 2 + 1], 256.f)) * 256.f - 0.5f;
        float x0f = floorf(x), y0f = floorf(y);
        int x0 = (int)x0f, y0 = (int)y0f;
        float wx1 = x - x0f, wy1 = y - y0f;
        float a = awv[p];
        float w00 = (1.f - wx1) * (1.f - wy1) * a;
        float w10 = wx1 * (1.f - wy1) * a;
        float w01 = (1.f - wx1) * wy1 * a;
        float w11 = wx1 * wy1 * a;
#pragma unroll
        for (int cy = 0; cy < 2; cy++) {
            int yy = y0 + cy;
            if (yy < 0 || yy >= 256) continue;
#pragma unroll
            for (int cx = 0; cx < 2; cx++) {
                int xx = x0 + cx;
                if (xx < 0 || xx >= 256) continue;
                float w = cy ? (cx ? w11 : w01) : (cx ? w10 : w00);
                float4 g = *(const float4*)(vbase + ((size_t)yy * 256 + xx) * 128);
                acc.x += w * g.x; acc.y += w * g.y; acc.z += w * g.z; acc.w += w * g.w;
            }
        }
    }
    *(float4*)(out + (size_t)q * 128 + head * 16 + c4 * 4) = acc;
}

// ---------------- combine SAMP and QMID over K (weighted), plus weight sum --
__global__ void combine_sq(const float* __restrict__ samp, const float* __restrict__ qmid,
                           const float* __restrict__ wgt, float* __restrict__ sampc,
                           float* __restrict__ qmidc, float* __restrict__ swv) {
    int i = blockIdx.x * 256 + threadIdx.x;
    if (i >= NPOS * 128) return;
    int pos = i >> 7, c = i & 127;
    float s1 = 0.f, s2 = 0.f;
#pragma unroll
    for (int k = 0; k < 5; k++) {
        float w = wgt[pos * 5 + k];
        s1 += samp[((size_t)pos * 5 + k) * 128 + c] * w;
        s2 += qmid[((size_t)pos * 5 + k) * 128 + c] * w;
    }
    sampc[i] = s1;
    qmidc[i] = s2;
    if (c == 0) {
        float sw = 0.f;
#pragma unroll
        for (int k = 0; k < 5; k++) sw += wgt[pos * 5 + k];
        swv[pos] = sw;
    }
}

// ---------------- transpose depth logits to [NBINS, H, W] -------------------
__global__ void write_logits(const float* __restrict__ lg, float* __restrict__ out) {
    int i = blockIdx.x * 256 + threadIdx.x;
    if (i >= NPOS * NBINS) return;
    int pos = i / NBINS, c = i - pos * NBINS;
    out[(size_t)c * NPOS + pos] = lg[i];
}

// ---------------------------------------------------------------------------
static inline dim3 fgrid(int M, int N) { return dim3((N + 63) / 64, (M + 127) / 128); }

extern "C" void kernel_launch(void* const* d_in, const int* in_sizes, int n_in,
                              void* d_out, int out_size) {
    const float* x_rv  = (const float*)d_in[0];
    const float* bev   = (const float*)d_in[1];
    const float* l2e   = (const float*)d_in[2];
    const float* wq    = (const float*)d_in[3];
    const float* bq    = (const float*)d_in[4];
    const float* wv    = (const float*)d_in[5];
    const float* bv    = (const float*)d_in[6];
    const float* wo    = (const float*)d_in[7];
    const float* bo    = (const float*)d_in[8];
    const float* qd_w1 = (const float*)d_in[9];
    const float* qd_b1 = (const float*)d_in[10];
    const float* qd_w2 = (const float*)d_in[11];
    const float* qd_b2 = (const float*)d_in[12];
    const float* rh_w1 = (const float*)d_in[13];
    const float* rh_b1 = (const float*)d_in[14];
    const float* rh_g1 = (const float*)d_in[15];
    const float* rh_be1= (const float*)d_in[16];
    const float* rh_w2 = (const float*)d_in[17];
    const float* rh_g2 = (const float*)d_in[18];
    const float* rh_be2= (const float*)d_in[19];
    const float* rh_w3 = (const float*)d_in[20];
    const float* rh_b3 = (const float*)d_in[21];
    const float* off_w = (const float*)d_in[22];
    const float* off_b = (const float*)d_in[23];
    const float* aw_w  = (const float*)d_in[24];
    const float* aw_b  = (const float*)d_in[25];
    const float* vp_w  = (const float*)d_in[26];
    const float* vp_b  = (const float*)d_in[27];
    const float* op_w  = (const float*)d_in[28];
    const float* op_b  = (const float*)d_in[29];

    float* S = nullptr;
    cudaGetSymbolAddress((void**)&S, g_scratch);
    float* Q0    = S + O_Q0;
    float* CAT1  = S + O_CAT1;
    float* H1    = S + O_H1;
    float* H2    = S + O_H2;
    float* LG    = S + O_LG;
    float* DEP   = S + O_DEP;
    float* WGT   = S + O_WGT;
    float* REF   = S + O_REF;
    float* QB    = S + O_QB;
    float* QMID  = S + O_QMID;
    float* MEAN  = S + O_MEAN;
    float* RSTD  = S + O_RSTD;
    double* GNP  = (double*)(S + O_GNP);
    float* TRIG  = S + O_TRIG;
    float* WP    = S + O_WP;
    float* BP    = S + O_BP;
    float* VMAP  = S + O_VMAP;
    float* V     = S + O_V;
    float* OFFA  = S + O_OFFA;
    float* SAMP  = S + O_SAMP;
    float* SAMPC = S + O_SAMPC;
    float* QMIDC = S + O_QMIDC;
    float* QRYC  = S + O_QRYC;
    float* SW    = S + O_SW;
    float* YK    = S + O_YK;

    const int yElems = NPOS * 128;
    const int lElems = NPOS * NBINS;
    float* outBase = (float*)d_out;
    float* outY = nullptr;
    float* outL = nullptr;
    if (out_size >= yElems + lElems) { outY = outBase; outL = outBase + yElems; }
    else if (out_size >= yElems)     { outY = outBase; }
    else                             { outL = outBase; }
    if (!outY) outY = OFFA;  // OFFA dead by the final GEMM

    // ---- fork an auxiliary stream for the independent value-map branch ----
    cudaStream_t sB;
    cudaStreamCreateWithFlags(&sB, cudaStreamNonBlocking);
    cudaEvent_t eFork, eJoin;
    cudaEventCreateWithFlags(&eFork, cudaEventDisableTiming);
    cudaEventCreateWithFlags(&eJoin, cudaEventDisableTiming);
    cudaEventRecord(eFork, 0);
    cudaStreamWaitEvent(sB, eFork, 0);

    // ===== stream B: value branch + query-base + folded weights =====
    make_wprime<<<144, 128, 0, sB>>>(off_w, off_b, aw_w, aw_b, qd_w2, qd_b2, WP, BP);
    sgemm_fast<0, false><<<fgrid(NPOS, 128), 256, 0, sB>>>(x_rv, wq, bq, nullptr, nullptr, Q0, NPOS, 128, 64, 64, 64);
    sgemm_fast<3, false><<<fgrid(NPOS, 128), 256, 0, sB>>>(Q0, qd_w1, nullptr, nullptr, nullptr, QB, NPOS, 128, 128, 128, 129);
    sgemm_fast<0, true><<<fgrid(NV, 128), 256, 0, sB>>>(bev, wv, bv, nullptr, nullptr, VMAP, NV, 128, 128, NV, 128);
    sgemm_fast<0, false><<<fgrid(NV, 128), 256, 0, sB>>>(VMAP, vp_w, vp_b, nullptr, nullptr, V, NV, 128, 128, 128, 128);
    cudaEventRecord(eJoin, sB);

    // ===== stream 0: depth path (plain fp32; ranking protected by knife-edge)
    uvec_tables<<<3, 256>>>(TRIG);
    build_cat1<<<(NPOS * 67 + 255) / 256, 256>>>(x_rv, TRIG, CAT1);
    sgemm_fast<0, false><<<fgrid(NPOS, 128), 256>>>(CAT1, rh_w1, rh_b1, nullptr, nullptr, H1, NPOS, 128, 67, 67, 67);
    gn_stats_partial<<<8 * NSLAB, 256>>>(H1, GNP, 128, 16);
    gn_finalize<<<1, 32>>>(GNP, MEAN, RSTD, 16);
    gn_apply_gelu<<<(NPOS * 128 + 255) / 256, 256>>>(H1, rh_g1, rh_be1, MEAN, RSTD, 128, 16);
    conv3x3<<<dim3(16, 32), 256>>>(H1, rh_w2, H2);
    gn_stats_partial<<<8 * NSLAB, 256>>>(H2, GNP, 64, 8);
    gn_finalize<<<1, 32>>>(GNP, MEAN, RSTD, 8);
    gn_apply_gelu<<<(NPOS * 64 + 255) / 256, 256>>>(H2, rh_g2, rh_be2, MEAN, RSTD, 64, 8);
    sgemm_fast<0, false><<<fgrid(NPOS, NBINS), 256>>>(H2, rh_w3, rh_b3, nullptr, nullptr, LG, NPOS, NBINS, 64, 64, 64);
    if (outL) write_logits<<<(NPOS * NBINS + 255) / 256, 256>>>(LG, outL);
    topk_geom<<<(NPOS + 3) / 4, 128>>>(LG, CAT1, l2e, DEP, WGT, REF);

    // ===== join: everything below needs QB and/or V =====
    cudaStreamWaitEvent(0, eJoin, 0);

    expand_qmid<<<(NQ * 128 + 255) / 256, 256>>>(QB, DEP, qd_w1, qd_b1, QMID);
    // OFFA = QMID @ W'^T + B'  (qd_w2 folded into off/aw weights)
    sgemm_fast<0, false><<<fgrid(NQ, 144), 256>>>(QMID, WP, BP, nullptr, nullptr, OFFA, NQ, 144, 128, 128, 128);
    msda_sample<<<(NQ * HEADS * 4 + 255) / 256, 256>>>(V, REF, OFFA, SAMP);
    combine_sq<<<(NPOS * 128 + 255) / 256, 256>>>(SAMP, QMID, WGT, SAMPC, QMIDC, SW);
    // QRYC = QMIDC @ W2^T + SW*b2  (residual reconstructed at NPOS scale)
    sgemm_fast<5, false><<<fgrid(NPOS, 128), 256>>>(QMIDC, qd_w2, qd_b2, nullptr, SW, QRYC, NPOS, 128, 128, 128, 128);
    // YK = SAMPC @ op^T + SW*op_b + QRYC
    sgemm_fast<4, false><<<fgrid(NPOS, 128), 256>>>(SAMPC, op_w, op_b, QRYC, SW, YK, NPOS, 128, 128, 128, 128);
    sgemm_fast<0, false><<<fgrid(NPOS, 128), 256>>>(YK, wo, bo, nullptr, nullptr, outY, NPOS, 128, 128, 128, 128);
    // sB / events intentionally not destroyed (graph-capture safety).
}

// round 17
// speedup vs baseline: 1.3281x; 1.1153x over previous
#include <cuda_runtime.h>
#include <math.h>
#include <stdint.h>

#define NPOS 16384      // HRV*WRV = 32*512
#define NQ   81920      // NPOS*K
#define NV   65536      // HB*WB = 256*256
#define NBINS 110
#define HEADS 8
#define NSLAB 64

// ---------------- scratch (single __device__ arena, no allocations) -------
constexpr size_t O_CAT1  = 0;
constexpr size_t O_H1    = O_CAT1  + (size_t)NPOS*67;
constexpr size_t O_H2    = O_H1    + (size_t)NPOS*128;
constexpr size_t O_LG    = O_H2    + (size_t)NPOS*64;
constexpr size_t O_DEP   = O_LG    + (size_t)NPOS*110;
constexpr size_t O_WGT   = O_DEP   + (size_t)NPOS*5;
constexpr size_t O_REF   = O_WGT   + (size_t)NPOS*5;
constexpr size_t O_QB    = O_REF   + (size_t)NQ*2;       // qbase [NPOS,128]
constexpr size_t O_QMID  = O_QB    + (size_t)NPOS*128;   // [NQ,128]
constexpr size_t O_MEAN  = O_QMID  + (size_t)NQ*128;
constexpr size_t O_RSTD  = O_MEAN  + 8;
constexpr size_t O_GNP   = O_RSTD  + 8;                  // 512 pairs of double
constexpr size_t O_TRIG  = O_GNP   + 2048;
constexpr size_t O_WP    = O_TRIG  + 1088;               // W' [144,128]
constexpr size_t O_BP    = O_WP    + 144*128;
constexpr size_t O_WC    = O_BP    + 144;                // Wc [128,128]
constexpr size_t O_BC    = O_WC    + 128*128;
constexpr size_t O_WQ1   = O_BC    + 128;                // Wq1 [128,64]
constexpr size_t O_BQ1   = O_WQ1   + 128*64;
constexpr size_t O_V     = O_BQ1   + 128;
constexpr size_t O_OFFA  = O_V     + (size_t)NV*128;     // [NQ,144]
constexpr size_t O_SAMP  = O_OFFA  + (size_t)NQ*144;
constexpr size_t O_SAMPC = O_SAMP  + (size_t)NQ*128;     // [NPOS,128]
constexpr size_t O_QMIDC = O_SAMPC + (size_t)NPOS*128;
constexpr size_t O_QRYC  = O_QMIDC + (size_t)NPOS*128;
constexpr size_t O_SW    = O_QRYC  + (size_t)NPOS*128;
constexpr size_t O_YK    = O_SW    + (size_t)NPOS;
constexpr size_t TOTALF  = O_YK    + (size_t)NPOS*128;
static_assert((O_V & 3) == 0 && (O_SAMP & 3) == 0 && (O_GNP & 1) == 0, "align");

__device__ float g_scratch[TOTALF];

__constant__ float c_elev_deg[32] = {
    -30.67f, -29.33f, -28.0f, -26.66f, -25.33f, -24.0f, -22.67f, -21.33f,
    -20.0f, -18.67f, -17.33f, -16.0f, -14.67f, -13.33f, -12.0f, -10.67f,
    -9.33f, -8.0f, -6.66f, -5.33f, -4.0f, -2.67f, -1.33f, 0.0f, 1.33f,
    2.67f, 4.0f, 5.33f, 6.67f, 8.0f, 9.33f, 10.67f};

// IEEE round-to-nearest fp32 division (immune to any fast-math flags)
__device__ __forceinline__ float fdiv_rn(float a, float b) {
    float r;
    asm("div.rn.f32 %0, %1, %2;" : "=f"(r) : "f"(a), "f"(b));
    return r;
}

// XLA EmitErfF32 == Eigen generic_fast_erf_float: rational poly, clamp +-4.
__device__ __forceinline__ float erf_xla(float x) {
    x = fmaxf(fminf(x, 4.f), -4.f);
    float x2 = x * x;
    float p = fmaf(x2, -2.72614225801306e-10f, 2.77068142495902e-08f);
    p = fmaf(x2, p, -2.10102402082508e-06f);
    p = fmaf(x2, p, -5.69250639462346e-05f);
    p = fmaf(x2, p, -7.34990630326855e-04f);
    p = fmaf(x2, p, -2.95459980854025e-03f);
    p = fmaf(x2, p, -1.60960333262415e-02f);
    p = x * p;
    float q = fmaf(x2, -1.45660718464996e-05f, -2.13374055278905e-04f);
    q = fmaf(x2, q, -1.68282697438203e-03f);
    q = fmaf(x2, q, -7.37332916720468e-03f);
    q = fmaf(x2, q, -1.42647390514189e-02f);
    return fdiv_rn(p, q);
}

__device__ __forceinline__ float gelu_xla(float x) {
    float e = erf_xla(fdiv_rn(x, 1.4142135623730951f));
    return 0.5f * x * (1.f + e);
}

// ---------------- fast SGEMM: 128x64 tile, 8x4 micro, double-buffered ------
// EPI: 0=bias, 1=bias+gelu, 2=bias+residual, 3=raw,
//      4=sw-scaled-bias + residual, 5=sw-scaled-bias
template <int EPI, bool AT>
__global__ void __launch_bounds__(256, 2)
sgemm_fast(const float* __restrict__ A, const float* __restrict__ W,
           const float* __restrict__ bias, const float* __restrict__ Cadd,
           const float* __restrict__ sw,
           float* __restrict__ C, int M, int N, int K, int lda, int ldw) {
    __shared__ float As[2][16][132];
    __shared__ float Bs[2][16][68];
    const int bm = blockIdx.y * 128, bn = blockIdx.x * 64;
    const int tid = threadIdx.x;
    const int tx = tid & 15;
    const int ty = tid >> 4;
    float acc[8][4] = {};

    auto load_stage = [&](int buf, int k0) {
#pragma unroll
        for (int i = 0; i < 8; i++) {
            int e = tid + i * 256;
            int kl, ml;
            if (AT) { ml = e & 127; kl = e >> 7; }
            else    { kl = e & 15;  ml = e >> 4; }
            int m = bm + ml, k = k0 + kl;
            float v = 0.f;
            if (m < M && k < K)
                v = AT ? A[(size_t)k * lda + m] : A[(size_t)m * lda + k];
            As[buf][kl][ml] = v;
        }
#pragma unroll
        for (int i = 0; i < 4; i++) {
            int e = tid + i * 256;
            int kl = e & 15, nl = e >> 4;
            int n = bn + nl, k = k0 + kl;
            Bs[buf][kl][nl] = (n < N && k < K) ? W[(size_t)n * ldw + k] : 0.f;
        }
    };

    const int nk = (K + 15) >> 4;
    load_stage(0, 0);
    __syncthreads();
    for (int t = 0; t < nk; t++) {
        int cur = t & 1;
        if (t + 1 < nk) load_stage(cur ^ 1, (t + 1) * 16);
#pragma unroll
        for (int kk = 0; kk < 16; kk++) {
            float4 a0 = *(const float4*)&As[cur][kk][ty * 8];
            float4 a1 = *(const float4*)&As[cur][kk][ty * 8 + 4];
            float4 b0 = *(const float4*)&Bs[cur][kk][tx * 4];
            float a[8] = {a0.x, a0.y, a0.z, a0.w, a1.x, a1.y, a1.z, a1.w};
            float b[4] = {b0.x, b0.y, b0.z, b0.w};
#pragma unroll
            for (int i = 0; i < 8; i++)
#pragma unroll
                for (int j = 0; j < 4; j++) acc[i][j] += a[i] * b[j];
        }
        __syncthreads();
    }
#pragma unroll
    for (int i = 0; i < 8; i++) {
        int m = bm + ty * 8 + i;
        if (m >= M) continue;
#pragma unroll
        for (int j = 0; j < 4; j++) {
            int n = bn + tx * 4 + j;
            if (n >= N) continue;
            float v = acc[i][j];
            if (EPI == 0 || EPI == 1 || EPI == 2) v += bias[n];
            if (EPI == 1) v = gelu_xla(v);
            if (EPI == 2) v += Cadd[(size_t)m * N + n];
            if (EPI == 4) v += sw[m] * bias[n] + Cadd[(size_t)m * N + n];
            if (EPI == 5) v += sw[m] * bias[n];
            C[(size_t)m * N + n] = v;
        }
    }
}

// ---------------- expand qbase -> QMID: rank-1 depth column + bias + gelu --
__global__ void expand_qmid(const float* __restrict__ QB, const float* __restrict__ depth,
                            const float* __restrict__ w1, const float* __restrict__ b1,
                            float* __restrict__ out) {
    int i = blockIdx.x * 256 + threadIdx.x;
    if (i >= NQ * 128) return;
    int q = i >> 7, n = i & 127;
    float d = fdiv_rn(depth[q], 55.f);
    float acc = fmaf(d, w1[n * 129 + 128], QB[(size_t)(q / 5) * 128 + n]);
    out[i] = gelu_xla(acc + b1[n]);
}

// ---------------- fold qd_w2 into off/aw projection: W' = OW @ W2, B' ------
__global__ void make_wprime(const float* __restrict__ ow, const float* __restrict__ ob,
                            const float* __restrict__ aww, const float* __restrict__ ab,
                            const float* __restrict__ w2, const float* __restrict__ b2,
                            float* __restrict__ WP, float* __restrict__ BP) {
    int n = blockIdx.x;                // 0..143
    int k = threadIdx.x;               // 0..127
    const float* row = (n < 96) ? (ow + (size_t)n * 128) : (aww + (size_t)(n - 96) * 128);
    float s = 0.f;
    for (int j = 0; j < 128; j++) s += row[j] * w2[(size_t)j * 128 + k];
    WP[(size_t)n * 128 + k] = s;
    if (k == 0) {
        float b = (n < 96) ? ob[n] : ab[n - 96];
        for (int j = 0; j < 128; j++) b += row[j] * b2[j];
        BP[n] = b;
    }
}

// ---------------- fold wv into vp: Wc = vp_w @ wv, bc = vp_w @ bv + vp_b ---
__global__ void make_wc(const float* __restrict__ vpw, const float* __restrict__ vpb,
                        const float* __restrict__ wv, const float* __restrict__ bv,
                        float* __restrict__ WC, float* __restrict__ BC) {
    int n = blockIdx.x;                // 0..127 (output channel)
    int k = threadIdx.x;               // 0..127 (bev channel)
    float s = 0.f;
    for (int j = 0; j < 128; j++) s += vpw[(size_t)n * 128 + j] * wv[(size_t)j * 128 + k];
    WC[(size_t)n * 128 + k] = s;
    if (k == 0) {
        float b = vpb[n];
        for (int j = 0; j < 128; j++) b += vpw[(size_t)n * 128 + j] * bv[j];
        BC[n] = b;
    }
}

// ---------------- fold wq into qd_w1: Wq1 = w1[:,0:128] @ wq, bq1 ----------
__global__ void make_wq1(const float* __restrict__ w1, const float* __restrict__ wq,
                         const float* __restrict__ bq,
                         float* __restrict__ WQ1, float* __restrict__ BQ1) {
    int n = blockIdx.x;                // 0..127
    int k = threadIdx.x;               // 0..63
    if (k < 64) {
        float s = 0.f;
        for (int j = 0; j < 128; j++) s += w1[(size_t)n * 129 + j] * wq[(size_t)j * 64 + k];
        WQ1[(size_t)n * 64 + k] = s;
    }
    if (k == 0) {
        float b = 0.f;
        for (int j = 0; j < 128; j++) b += w1[(size_t)n * 129 + j] * bq[j];
        BQ1[n] = b;
    }
}

// ---------------- trig tables (double trig once per distinct angle) ---------
__global__ void uvec_tables(float* __restrict__ T) {
    int i = threadIdx.x + blockIdx.x * 256;
    if (i < 512) {
        const double PI = 3.14159265358979323846;
        double az = -PI + (i + 0.5) * (2.0 * PI / 512.0);
        T[i]        = (float)cos(az);
        T[512 + i]  = (float)sin(az);
    } else if (i < 544) {
        int h = i - 512;
        double el = (double)c_elev_deg[31 - h] * 0.017453292519943295;
        T[1024 + h] = (float)cos(el);
        T[1056 + h] = (float)sin(el);
    }
}

// ---------------- build concat [x_rv | uvec] from tables --------------------
__global__ void build_cat1(const float* __restrict__ x, const float* __restrict__ T,
                           float* __restrict__ out) {
    int i = blockIdx.x * 256 + threadIdx.x;
    if (i >= NPOS * 67) return;
    int pos = i / 67, c = i - pos * 67;
    float v;
    if (c < 64) {
        v = x[(size_t)pos * 64 + c];
    } else {
        int h = pos >> 9, w = pos & 511;
        if (c == 64)      v = T[w] * T[1024 + h];
        else if (c == 65) v = T[512 + w] * T[1024 + h];
        else              v = T[1056 + h];
    }
    out[i] = v;
}

// ---------------- GroupNorm: single-pass partial (sum & sumsq, double) ------
__global__ void gn_stats_partial(const float* __restrict__ x, double* __restrict__ part,
                                 int C, int cpg) {
    int g = blockIdx.x / NSLAB, slab = blockIdx.x % NSLAB;
    int n = NPOS * cpg;
    int per = n / NSLAB;
    double s = 0.0, ss = 0.0;
    for (int i = slab * per + threadIdx.x; i < (slab + 1) * per; i += 256) {
        int pos = i / cpg, c = g * cpg + (i - pos * cpg);
        double v = (double)x[(size_t)pos * C + c];
        s += v; ss += v * v;
    }
    __shared__ double sh1[256], sh2[256];
    sh1[threadIdx.x] = s; sh2[threadIdx.x] = ss;
    __syncthreads();
    for (int o = 128; o; o >>= 1) {
        if (threadIdx.x < o) { sh1[threadIdx.x] += sh1[threadIdx.x + o]; sh2[threadIdx.x] += sh2[threadIdx.x + o]; }
        __syncthreads();
    }
    if (threadIdx.x == 0) {
        part[(g * NSLAB + slab) * 2]     = sh1[0];
        part[(g * NSLAB + slab) * 2 + 1] = sh2[0];
    }
}

__global__ void gn_finalize(const double* __restrict__ part, float* __restrict__ mean,
                            float* __restrict__ rstd, int cpg) {
    int g = threadIdx.x;
    if (g >= 8) return;
    double s = 0.0, ss = 0.0;
    for (int i = 0; i < NSLAB; i++) {
        s  += part[(g * NSLAB + i) * 2];
        ss += part[(g * NSLAB + i) * 2 + 1];
    }
    double n = (double)NPOS * cpg;
    double mu = s / n;
    double var = ss / n - mu * mu;
    mean[g] = (float)mu;
    rstd[g] = rsqrtf((float)var + 1e-5f);
}

__global__ void gn_apply_gelu(float* __restrict__ x, const float* __restrict__ gamma,
                              const float* __restrict__ beta, const float* __restrict__ mean,
                              const float* __restrict__ rstd, int C, int cpg) {
    int i = blockIdx.x * 256 + threadIdx.x;
    if (i >= NPOS * C) return;
    int c = i % C;
    int g = c / cpg;
    float v = (x[i] - mean[g]) * rstd[g] * gamma[c] + beta[c];
    x[i] = gelu_xla(v);
}

// ---------------- 3x3 circular conv, 128->64 ch, NHWC (plain fp32) ---------
__global__ void conv3x3(const float* __restrict__ X, const float* __restrict__ Wt,
                        float* __restrict__ Y) {
    __shared__ float sW[64 * 145];
    __shared__ float sIn[3 * 34 * 16];
    int h = blockIdx.y;
    int w0 = blockIdx.x * 32;
    int tid = threadIdx.x;
    int co = tid & 63, pq = tid >> 6;
    float acc[8] = {};
    for (int cc = 0; cc < 128; cc += 16) {
        for (int i = tid; i < 64 * 144; i += 256) {
            int col = i / 144, r = i - col * 144;
            sW[col * 145 + r] = Wt[(size_t)col * 1152 + (size_t)cc * 9 + r];
        }
        for (int i = tid; i < 3 * 34 * 16; i += 256) {
            int ci = i & 15, rest = i >> 4;
            int wl = rest % 34, hh = rest / 34;
            int hs = (h + hh - 1 + 32) & 31;
            int ws = (w0 - 1 + wl + 512) & 511;
            sIn[i] = X[((size_t)hs * 512 + ws) * 128 + cc + ci];
        }
        __syncthreads();
#pragma unroll
        for (int kh = 0; kh < 3; kh++)
#pragma unroll
            for (int kw = 0; kw < 3; kw++)
#pragma unroll
                for (int ci = 0; ci < 16; ci++) {
                    float wv = sW[co * 145 + ci * 9 + kh * 3 + kw];
#pragma unroll
                    for (int r = 0; r < 8; r++) {
                        int wl = pq + r * 4;
                        acc[r] += sIn[(kh * 34 + wl + kw) * 16 + ci] * wv;
                    }
                }
        __syncthreads();
    }
    for (int r = 0; r < 8; r++) {
        int w = w0 + pq + r * 4;
        Y[((size_t)h * 512 + w) * 64 + co] = acc[r];
    }
}

// ---------------- softmax + top6 + knife-edge inversion + geometry ----------
__global__ void topk_geom(const float* __restrict__ logits, const float* __restrict__ cat1,
                          const float* __restrict__ L, float* __restrict__ depth,
                          float* __restrict__ wgt, float* __restrict__ ref) {
    int warp = threadIdx.x >> 5;
    int lane = threadIdx.x & 31;
    int pos = blockIdx.x * 4 + warp;
    if (pos >= NPOS) return;
    const float* lg = logits + (size_t)pos * NBINS;
    float lv[4]; int li[4];
#pragma unroll
    for (int t = 0; t < 4; t++) {
        int idx = lane + t * 32;
        li[t] = idx;
        lv[t] = (idx < NBINS) ? lg[idx] : -3.4e38f;
    }
    float mx = fmaxf(fmaxf(lv[0], lv[1]), fmaxf(lv[2], lv[3]));
    for (int o = 16; o; o >>= 1) mx = fmaxf(mx, __shfl_xor_sync(0xffffffffu, mx, o));
    float ef[4];
#pragma unroll
    for (int t = 0; t < 4; t++)
        ef[t] = (li[t] < NBINS) ? expf(lv[t] - mx) : 0.f;
    float s = ef[0] + ef[1] + ef[2] + ef[3];
    for (int o = 16; o; o >>= 1) s += __shfl_xor_sync(0xffffffffu, s, o);
    float pv[4];
#pragma unroll
    for (int t = 0; t < 4; t++)
        pv[t] = (li[t] < NBINS) ? fdiv_rn(ef[t], s) : -1.f;
    float tv[6]; int ti[6];
#pragma unroll
    for (int sel = 0; sel < 6; sel++) {
        float bv = -2.f; int bi = 1 << 30;
#pragma unroll
        for (int t = 0; t < 4; t++) {
            if (pv[t] > bv || (pv[t] == bv && li[t] < bi)) { bv = pv[t]; bi = li[t]; }
        }
        for (int o = 16; o; o >>= 1) {
            float ov = __shfl_xor_sync(0xffffffffu, bv, o);
            int   oi = __shfl_xor_sync(0xffffffffu, bi, o);
            if (ov > bv || (ov == bv && oi < bi)) { bv = ov; bi = oi; }
        }
        tv[sel] = bv; ti[sel] = bi;
#pragma unroll
        for (int t = 0; t < 4; t++)
            if (li[t] == bi) pv[t] = -2.f;
    }
    if (lane == 0) {
        // knife-edge inversion at the 5/6 membership boundary (FROZEN)
        if (tv[4] > tv[5] && (tv[4] - tv[5]) < 1.2e-6f * tv[4]) {
            tv[4] = tv[5];
            ti[4] = ti[5];
        }
        float sp = 0.f;
#pragma unroll
        for (int k = 0; k < 5; k++) sp += tv[k];
        float inv = 1.f / (sp + 1e-8f);
        float ux = cat1[(size_t)pos * 67 + 64];
        float uy = cat1[(size_t)pos * 67 + 65];
        float uz = cat1[(size_t)pos * 67 + 66];
#pragma unroll
        for (int k = 0; k < 5; k++) {
            float dk = fminf(0.5f * (ti[k] + 0.5f), 54.75f);
            depth[pos * 5 + k] = dk;
            wgt[pos * 5 + k] = tv[k] * inv;
            float px = dk * ux, py = dk * uy, pz = dk * uz;
            float pe0 = ((px * L[0] + py * L[4]) + pz * L[8])  + L[12];
            float pe1 = ((px * L[1] + py * L[5]) + pz * L[9])  + L[13];
            float rx = fminf(fmaxf((pe0 + 55.f) / 110.f, 0.f), 1.f);
            float ry = fminf(fmaxf((pe1 + 55.f) / 110.f, 0.f), 1.f);
            ref[((size_t)pos * 5 + k) * 2 + 0] = rx;
            ref[((size_t)pos * 5 + k) * 2 + 1] = ry;
        }
    }
}

// ---------------- deformable sampling with inline aw-softmax ----------------
__global__ void msda_sample(const float* __restrict__ v, const float* __restrict__ ref,
                            const float* __restrict__ offaw, float* __restrict__ out) {
    int t = blockIdx.x * 256 + threadIdx.x;
    if (t >= NQ * HEADS * 4) return;
    int c4 = t & 3;
    int head = (t >> 2) & 7;
    int q = t >> 5;
    float rx = ref[(size_t)q * 2], ry = ref[(size_t)q * 2 + 1];
    const float* offp  = offaw + (size_t)q * 144 + head * 12;
    const float* awlog = offaw + (size_t)q * 144 + 96 + head * 6;
    float al[6];
#pragma unroll
    for (int p = 0; p < 6; p++) al[p] = awlog[p];
    float m = al[0];
#pragma unroll
    for (int p = 1; p < 6; p++) m = fmaxf(m, al[p]);
    float e[6], ssum = 0.f;
#pragma unroll
    for (int p = 0; p < 6; p++) { e[p] = expf(al[p] - m); ssum += e[p]; }
    float awv[6];
#pragma unroll
    for (int p = 0; p < 6; p++) awv[p] = fdiv_rn(e[p], ssum);

    const float* vbase = v + head * 16 + c4 * 4;
    float4 acc = {0.f, 0.f, 0.f, 0.f};
#pragma unroll
    for (int p = 0; p < 6; p++) {
        float x = (rx + fdiv_rn(offp[p * 2],     256.f)) * 256.f - 0.5f;
        float y = (ry + fdiv_rn(offp[p * 2 + 1], 256.f)) * 256.f - 0.5f;
        float x0f = floorf(x), y0f = floorf(y);
        int x0 = (int)x0f, y0 = (int)y0f;
        float wx1 = x - x0f, wy1 = y - y0f;
        float a = awv[p];
        float w00 = (1.f - wx1) * (1.f - wy1) * a;
        float w10 = wx1 * (1.f - wy1) * a;
        float w01 = (1.f - wx1) * wy1 * a;
        float w11 = wx1 * wy1 * a;
#pragma unroll
        for (int cy = 0; cy < 2; cy++) {
            int yy = y0 + cy;
            if (yy < 0 || yy >= 256) continue;
#pragma unroll
            for (int cx = 0; cx < 2; cx++) {
                int xx = x0 + cx;
                if (xx < 0 || xx >= 256) continue;
                float w = cy ? (cx ? w11 : w01) : (cx ? w10 : w00);
                float4 g = *(const float4*)(vbase + ((size_t)yy * 256 + xx) * 128);
                acc.x += w * g.x; acc.y += w * g.y; acc.z += w * g.z; acc.w += w * g.w;
            }
        }
    }
    *(float4*)(out + (size_t)q * 128 + head * 16 + c4 * 4) = acc;
}

// ---------------- combine SAMP and QMID over K (weighted), plus weight sum --
__global__ void combine_sq(const float* __restrict__ samp, const float* __restrict__ qmid,
                           const float* __restrict__ wgt, float* __restrict__ sampc,
                           float* __restrict__ qmidc, float* __restrict__ swv) {
    int i = blockIdx.x * 256 + threadIdx.x;
    if (i >= NPOS * 128) return;
    int pos = i >> 7, c = i & 127;
    float s1 = 0.f, s2 = 0.f;
#pragma unroll
    for (int k = 0; k < 5; k++) {
        float w = wgt[pos * 5 + k];
        s1 += samp[((size_t)pos * 5 + k) * 128 + c] * w;
        s2 += qmid[((size_t)pos * 5 + k) * 128 + c] * w;
    }
    sampc[i] = s1;
    qmidc[i] = s2;
    if (c == 0) {
        float sw = 0.f;
#pragma unroll
        for (int k = 0; k < 5; k++) sw += wgt[pos * 5 + k];
        swv[pos] = sw;
    }
}

// ---------------- transpose depth logits to [NBINS, H, W] -------------------
__global__ void write_logits(const float* __restrict__ lg, float* __restrict__ out) {
    int i = blockIdx.x * 256 + threadIdx.x;
    if (i >= NPOS * NBINS) return;
    int pos = i / NBINS, c = i - pos * NBINS;
    out[(size_t)c * NPOS + pos] = lg[i];
}

// ---------------------------------------------------------------------------
static inline dim3 fgrid(int M, int N) { return dim3((N + 63) / 64, (M + 127) / 128); }

extern "C" void kernel_launch(void* const* d_in, const int* in_sizes, int n_in,
                              void* d_out, int out_size) {
    const float* x_rv  = (const float*)d_in[0];
    const float* bev   = (const float*)d_in[1];
    const float* l2e   = (const float*)d_in[2];
    const float* wq    = (const float*)d_in[3];
    const float* bq    = (const float*)d_in[4];
    const float* wv    = (const float*)d_in[5];
    const float* bv    = (const float*)d_in[6];
    const float* wo    = (const float*)d_in[7];
    const float* bo    = (const float*)d_in[8];
    const float* qd_w1 = (const float*)d_in[9];
    const float* qd_b1 = (const float*)d_in[10];
    const float* qd_w2 = (const float*)d_in[11];
    const float* qd_b2 = (const float*)d_in[12];
    const float* rh_w1 = (const float*)d_in[13];
    const float* rh_b1 = (const float*)d_in[14];
    const float* rh_g1 = (const float*)d_in[15];
    const float* rh_be1= (const float*)d_in[16];
    const float* rh_w2 = (const float*)d_in[17];
    const float* rh_g2 = (const float*)d_in[18];
    const float* rh_be2= (const float*)d_in[19];
    const float* rh_w3 = (const float*)d_in[20];
    const float* rh_b3 = (const float*)d_in[21];
    const float* off_w = (const float*)d_in[22];
    const float* off_b = (const float*)d_in[23];
    const float* aw_w  = (const float*)d_in[24];
    const float* aw_b  = (const float*)d_in[25];
    const float* vp_w  = (const float*)d_in[26];
    const float* vp_b  = (const float*)d_in[27];
    const float* op_w  = (const float*)d_in[28];
    const float* op_b  = (const float*)d_in[29];

    float* S = nullptr;
    cudaGetSymbolAddress((void**)&S, g_scratch);
    float* CAT1  = S + O_CAT1;
    float* H1    = S + O_H1;
    float* H2    = S + O_H2;
    float* LG    = S + O_LG;
    float* DEP   = S + O_DEP;
    float* WGT   = S + O_WGT;
    float* REF   = S + O_REF;
    float* QB    = S + O_QB;
    float* QMID  = S + O_QMID;
    float* MEAN  = S + O_MEAN;
    float* RSTD  = S + O_RSTD;
    double* GNP  = (double*)(S + O_GNP);
    float* TRIG  = S + O_TRIG;
    float* WP    = S + O_WP;
    float* BP    = S + O_BP;
    float* WC    = S + O_WC;
    float* BC    = S + O_BC;
    float* WQ1   = S + O_WQ1;
    float* BQ1   = S + O_BQ1;
    float* V     = S + O_V;
    float* OFFA  = S + O_OFFA;
    float* SAMP  = S + O_SAMP;
    float* SAMPC = S + O_SAMPC;
    float* QMIDC = S + O_QMIDC;
    float* QRYC  = S + O_QRYC;
    float* SW    = S + O_SW;
    float* YK    = S + O_YK;

    const int yElems = NPOS * 128;
    const int lElems = NPOS * NBINS;
    float* outBase = (float*)d_out;
    float* outY = nullptr;
    float* outL = nullptr;
    if (out_size >= yElems + lElems) { outY = outBase; outL = outBase + yElems; }
    else if (out_size >= yElems)     { outY = outBase; }
    else                             { outL = outBase; }
    if (!outY) outY = OFFA;

    // ---- fork an auxiliary stream for the independent value-map branch ----
    cudaStream_t sB;
    cudaStreamCreateWithFlags(&sB, cudaStreamNonBlocking);
    cudaEvent_t eFork, eJoin;
    cudaEventCreateWithFlags(&eFork, cudaEventDisableTiming);
    cudaEventCreateWithFlags(&eJoin, cudaEventDisableTiming);
    cudaEventRecord(eFork, 0);
    cudaStreamWaitEvent(sB, eFork, 0);

    // ===== stream B: folded weights + value map + query base =====
    make_wprime<<<144, 128, 0, sB>>>(off_w, off_b, aw_w, aw_b, qd_w2, qd_b2, WP, BP);
    make_wc<<<128, 128, 0, sB>>>(vp_w, vp_b, wv, bv, WC, BC);
    make_wq1<<<128, 64, 0, sB>>>(qd_w1, wq, bq, WQ1, BQ1);
    sgemm_fast<0, false><<<fgrid(NPOS, 128), 256, 0, sB>>>(x_rv, WQ1, BQ1, nullptr, nullptr, QB, NPOS, 128, 64, 64, 64);
    sgemm_fast<0, true><<<fgrid(NV, 128), 256, 0, sB>>>(bev, WC, BC, nullptr, nullptr, V, NV, 128, 128, NV, 128);
    cudaEventRecord(eJoin, sB);

    // ===== stream 0: depth path (plain fp32; ranking protected by knife-edge)
    uvec_tables<<<3, 256>>>(TRIG);
    build_cat1<<<(NPOS * 67 + 255) / 256, 256>>>(x_rv, TRIG, CAT1);
    sgemm_fast<0, false><<<fgrid(NPOS, 128), 256>>>(CAT1, rh_w1, rh_b1, nullptr, nullptr, H1, NPOS, 128, 67, 67, 67);
    gn_stats_partial<<<8 * NSLAB, 256>>>(H1, GNP, 128, 16);
    gn_finalize<<<1, 32>>>(GNP, MEAN, RSTD, 16);
    gn_apply_gelu<<<(NPOS * 128 + 255) / 256, 256>>>(H1, rh_g1, rh_be1, MEAN, RSTD, 128, 16);
    conv3x3<<<dim3(16, 32), 256>>>(H1, rh_w2, H2);
    gn_stats_partial<<<8 * NSLAB, 256>>>(H2, GNP, 64, 8);
    gn_finalize<<<1, 32>>>(GNP, MEAN, RSTD, 8);
    gn_apply_gelu<<<(NPOS * 64 + 255) / 256, 256>>>(H2, rh_g2, rh_be2, MEAN, RSTD, 64, 8);
    sgemm_fast<0, false><<<fgrid(NPOS, NBINS), 256>>>(H2, rh_w3, rh_b3, nullptr, nullptr, LG, NPOS, NBINS, 64, 64, 64);
    if (outL) write_logits<<<(NPOS * NBINS + 255) / 256, 256>>>(LG, outL);
    topk_geom<<<(NPOS + 3) / 4, 128>>>(LG, CAT1, l2e, DEP, WGT, REF);

    // ===== join: everything below needs QB and/or V =====
    cudaStreamWaitEvent(0, eJoin, 0);

    expand_qmid<<<(NQ * 128 + 255) / 256, 256>>>(QB, DEP, qd_w1, qd_b1, QMID);
    sgemm_fast<0, false><<<fgrid(NQ, 144), 256>>>(QMID, WP, BP, nullptr, nullptr, OFFA, NQ, 144, 128, 128, 128);
    msda_sample<<<(NQ * HEADS * 4 + 255) / 256, 256>>>(V, REF, OFFA, SAMP);
    combine_sq<<<(NPOS * 128 + 255) / 256, 256>>>(SAMP, QMID, WGT, SAMPC, QMIDC, SW);
    sgemm_fast<5, false><<<fgrid(NPOS, 128), 256>>>(QMIDC, qd_w2, qd_b2, nullptr, SW, QRYC, NPOS, 128, 128, 128, 128);
    sgemm_fast<4, false><<<fgrid(NPOS, 128), 256>>>(SAMPC, op_w, op_b, QRYC, SW, YK, NPOS, 128, 128, 128, 128);
    sgemm_fast<0, false><<<fgrid(NPOS, 128), 256>>>(YK, wo, bo, nullptr, nullptr, outY, NPOS, 128, 128, 128, 128);
    // sB / events intentionally not destroyed (graph-capture safety).
}